// round 17
// baseline (speedup 1.0000x reference)
#include <cuda_runtime.h>
#include <cuda_fp16.h>
#include <cstdint>

#define NPIX 4096
#define CC   256
#define CQ   64
#define BB   8
#define ROWS_ALL 384
#define LD   72    // attn smem row stride (halves)
#define LDW  264   // proj W tile stride (halves)
#define LDX  136   // proj x tile stride (halves)
#define LDT  136   // proj transpose-stage stride (halves)

// ================= scratch (device globals) =================
__device__ __half g_Q[(size_t)BB*NPIX*CQ];   // [b][n][cq]
__device__ __half g_K[(size_t)BB*NPIX*CQ];   // [b][m][cq]
__device__ __half g_V[(size_t)BB*CC*NPIX];   // [b][c][n]  (gamma folded)
__device__ __half g_xh[(size_t)BB*CC*NPIX];  // x in fp16, [b][k][n]
__device__ __half g_Wh[ROWS_ALL*CC];         // fused weights fp16 [row][k]
__device__ float  g_ball[ROWS_ALL];

// ================= PTX helpers =================
__device__ __forceinline__ uint32_t smem_u32(const void* p) {
    uint32_t a;
    asm("{ .reg .u64 t; cvta.to.shared.u64 t, %1; cvt.u32.u64 %0, t; }" : "=r"(a) : "l"(p));
    return a;
}
__device__ __forceinline__ void cpa16(uint32_t dst, const void* src) {
    asm volatile("cp.async.cg.shared.global [%0], [%1], 16;" :: "r"(dst), "l"(src));
}
#define CP_COMMIT() asm volatile("cp.async.commit_group;" ::: "memory")
#define CP_WAIT0()  asm volatile("cp.async.wait_group 0;" ::: "memory")

__device__ __forceinline__ void ldsm4(uint32_t r[4], uint32_t addr) {
    asm volatile("ldmatrix.sync.aligned.m8n8.x4.shared.b16 {%0,%1,%2,%3}, [%4];"
        : "=r"(r[0]), "=r"(r[1]), "=r"(r[2]), "=r"(r[3]) : "r"(addr));
}
__device__ __forceinline__ void ldsm4t(uint32_t r[4], uint32_t addr) {
    asm volatile("ldmatrix.sync.aligned.m8n8.x4.trans.shared.b16 {%0,%1,%2,%3}, [%4];"
        : "=r"(r[0]), "=r"(r[1]), "=r"(r[2]), "=r"(r[3]) : "r"(addr));
}
__device__ __forceinline__ void mmah(float c[4], const uint32_t a[4],
                                     uint32_t b0, uint32_t b1) {
    asm volatile(
        "mma.sync.aligned.m16n8k16.row.col.f32.f16.f16.f32 "
        "{%0,%1,%2,%3}, {%4,%5,%6,%7}, {%8,%9}, {%0,%1,%2,%3};"
        : "+f"(c[0]), "+f"(c[1]), "+f"(c[2]), "+f"(c[3])
        : "r"(a[0]), "r"(a[1]), "r"(a[2]), "r"(a[3]), "r"(b0), "r"(b1));
}
__device__ __forceinline__ uint32_t packh(float e0, float e1) {
    uint32_t r; asm("cvt.rn.f16x2.f32 %0, %1, %2;" : "=r"(r) : "f"(e1), "f"(e0)); return r;
}
// elu without /N (deferred): MUFU-based exp
__device__ __forceinline__ float elu_raw(float v) {
    float e;
    asm("ex2.approx.f32 %0, %1;" : "=f"(e) : "f"(v * 1.44269504f));
    return v > 0.f ? v : e - 1.0f;
}

// ============ Kernel 0: fused weights-build (gamma@V) + x->fp16 ============
__global__ void __launch_bounds__(256) prep_kernel(
        const float* __restrict__ x,
        const float* __restrict__ qw, const float* __restrict__ qb,
        const float* __restrict__ kw, const float* __restrict__ kb,
        const float* __restrict__ vw, const float* __restrict__ vb,
        const float* __restrict__ gw) {
    int bid = blockIdx.x;
    if (bid < ROWS_ALL) {
        int r = bid, d = threadIdx.x;
        if (r < CQ) {
            g_Wh[r*CC + d] = __float2half(qw[r*CC + d]);
            if (d == 0) g_ball[r] = qb[r];
        } else if (r < 2*CQ) {
            g_Wh[r*CC + d] = __float2half(kw[(r-CQ)*CC + d]);
            if (d == 0) g_ball[r] = kb[r-CQ];
        } else {
            int c = r - 2*CQ;
            float a[8];
            #pragma unroll
            for (int u = 0; u < 8; u++) a[u] = 0.f;
            #pragma unroll 4
            for (int cp = 0; cp < CC; cp += 8) {
                #pragma unroll
                for (int u = 0; u < 8; u++)
                    a[u] = fmaf(gw[c*CC + cp + u], vw[(cp + u)*CC + d], a[u]);
            }
            float s = ((a[0]+a[1]) + (a[2]+a[3])) + ((a[4]+a[5]) + (a[6]+a[7]));
            g_Wh[r*CC + d] = __float2half(s);
            if (d == 0) {
                float b0 = 0.f, b1 = 0.f, b2 = 0.f, b3 = 0.f;
                #pragma unroll 4
                for (int cp = 0; cp < CC; cp += 4) {
                    b0 = fmaf(gw[c*CC + cp],     vb[cp],     b0);
                    b1 = fmaf(gw[c*CC + cp + 1], vb[cp + 1], b1);
                    b2 = fmaf(gw[c*CC + cp + 2], vb[cp + 2], b2);
                    b3 = fmaf(gw[c*CC + cp + 3], vb[cp + 3], b3);
                }
                g_ball[r] = (b0 + b1) + (b2 + b3);
            }
        }
    } else {
        // cvt region: 2048 blocks, nq = 2097152 quads, exactly 4 per thread.
        // 4 independent load/convert/store streams for MLP=4.
        const size_t stride = (size_t)2048 * 256;
        size_t base = (size_t)(bid - ROWS_ALL)*256 + threadIdx.x;
        float4 v0 = *(const float4*)(x + (base             )*4);
        float4 v1 = *(const float4*)(x + (base +   stride  )*4);
        float4 v2 = *(const float4*)(x + (base + 2*stride  )*4);
        float4 v3 = *(const float4*)(x + (base + 3*stride  )*4);
        uint2 o0 = { packh(v0.x, v0.y), packh(v0.z, v0.w) };
        uint2 o1 = { packh(v1.x, v1.y), packh(v1.z, v1.w) };
        uint2 o2 = { packh(v2.x, v2.y), packh(v2.z, v2.w) };
        uint2 o3 = { packh(v3.x, v3.y), packh(v3.z, v3.w) };
        *(uint2*)(g_xh + (base             )*4) = o0;
        *(uint2*)(g_xh + (base +   stride  )*4) = o1;
        *(uint2*)(g_xh + (base + 2*stride  )*4) = o2;
        *(uint2*)(g_xh + (base + 3*stride  )*4) = o3;
    }
}

// ================= Kernel 1: projection via HMMA (unchanged) ===============
#define PW_O 0
#define PX_ST(s) (33792 + (s)*4352)
#define PROJ_SMEM 84992

__global__ void __launch_bounds__(256) proj_mma(const float* __restrict__ unused) {
    extern __shared__ __half psm[];
    const uint32_t sb = smem_u32(psm);
    const int tid = threadIdx.x, wid = tid >> 5, lane = tid & 31;
    const int g = lane >> 2, t4 = lane & 3;
    const int lrow = lane & 15, lcol = (lane >> 4) * 8;
    const int b = blockIdx.z, co0 = blockIdx.y * 128, n0 = blockIdx.x * 128;

    const int wc = (wid & 3) * 32;
    const int wn = (wid >> 2) * 64;

    #define PSB(idx) (sb + (uint32_t)(idx) * 2u)

    {
        const __half* wsrc = g_Wh + (size_t)co0 * CC;
        #pragma unroll
        for (int r = 0; r < 16; r++) {
            int id = tid + 256*r, row = id >> 5, ch = (id & 31) * 8;
            cpa16(PSB(PW_O + row*LDW + ch), wsrc + (size_t)row*CC + ch);
        }
        const __half* xsrc = g_xh + ((size_t)b*CC + 0)*NPIX + n0;
        #pragma unroll
        for (int r = 0; r < 2; r++) {
            int id = tid + 256*r, k = id >> 4, ch = (id & 15) * 8;
            cpa16(PSB(PX_ST(0) + k*LDX + ch), xsrc + (size_t)k*NPIX + ch);
        }
        CP_COMMIT();
    }

    float acc[2][8][4];
    #pragma unroll
    for (int i = 0; i < 2; i++)
        #pragma unroll
        for (int j = 0; j < 8; j++)
            #pragma unroll
            for (int q = 0; q < 4; q++) acc[i][j][q] = 0.f;

    for (int kc = 0; kc < 8; ++kc) {
        const int buf = kc & 1;
        CP_WAIT0();
        __syncthreads();
        if (kc < 7) {
            const __half* xsrc = g_xh + ((size_t)b*CC + (kc+1)*32)*NPIX + n0;
            #pragma unroll
            for (int r = 0; r < 2; r++) {
                int id = tid + 256*r, k = id >> 4, ch = (id & 15) * 8;
                cpa16(PSB(PX_ST(buf^1) + k*LDX + ch), xsrc + (size_t)k*NPIX + ch);
            }
            CP_COMMIT();
        }
        const uint32_t XO = PX_ST(buf);
        #pragma unroll
        for (int ks = 0; ks < 2; ++ks) {
            const int kk = kc*32 + ks*16;
            uint32_t a0[4], a1[4];
            ldsm4(a0, PSB(PW_O + (wc      + lrow)*LDW + kk + lcol));
            ldsm4(a1, PSB(PW_O + (wc + 16 + lrow)*LDW + kk + lcol));
            #pragma unroll
            for (int nt = 0; nt < 4; ++nt) {
                uint32_t bx[4];
                ldsm4t(bx, PSB(XO + (ks*16 + lrow)*LDX + wn + nt*16 + lcol));
                mmah(acc[0][2*nt],   a0, bx[0], bx[1]);
                mmah(acc[0][2*nt+1], a0, bx[2], bx[3]);
                mmah(acc[1][2*nt],   a1, bx[0], bx[1]);
                mmah(acc[1][2*nt+1], a1, bx[2], bx[3]);
            }
        }
        __syncthreads();
    }

    if (co0 >= 128) {
        #pragma unroll
        for (int i = 0; i < 2; i++) {
            #pragma unroll
            for (int h = 0; h < 2; h++) {
                int col = wc + 16*i + g + 8*h;
                int c = co0 - 128 + col;
                float bias = g_ball[co0 + col];
                __half* dst = g_V + ((size_t)b*CC + c)*NPIX + n0;
                #pragma unroll
                for (int j = 0; j < 8; j++) {
                    int n = wn + 8*j + t4*2;
                    *(uint32_t*)(dst + n) =
                        packh(acc[i][j][2*h] + bias, acc[i][j][2*h+1] + bias);
                }
            }
        }
    } else {
        __syncthreads();
        #pragma unroll
        for (int i = 0; i < 2; i++)
            #pragma unroll
            for (int h = 0; h < 2; h++) {
                int col = wc + 16*i + g + 8*h;
                float bias = g_ball[col];
                #pragma unroll
                for (int j = 0; j < 8; j++) {
                    int n = wn + 8*j + t4*2;
                    psm[PW_O + n*LDT + col]     = __float2half(acc[i][j][2*h]   + bias);
                    psm[PW_O + (n+1)*LDT + col] = __float2half(acc[i][j][2*h+1] + bias);
                }
            }
        __syncthreads();
        #pragma unroll
        for (int r = 0; r < 8; r++) {
            int id = tid + 256*r, nl = id >> 4, ch = id & 15;
            uint4 v = *(uint4*)&psm[PW_O + nl*LDT + ch*8];
            size_t nglob = (size_t)b*NPIX + n0 + nl;
            if (ch < 8) *(uint4*)(g_Q + nglob*CQ + ch*8) = v;
            else        *(uint4*)(g_K + nglob*CQ + (ch-8)*8) = v;
        }
    }
}

// ===== Kernel 2: fused attention (R16 structure, unchanged) ================
#define SM_K  0
#define SM_S  4608
#define Q_ST(s) (9216 + (s)*4608)
#define V_ST(s) (18432 + (s)*18432)
#define SMEM_HALVES (18432 + 2*18432)
#define SMEM_BYTES  (SMEM_HALVES*2)

__global__ void __launch_bounds__(256, 2) attn_mma(float* __restrict__ out,
                                                   const float* __restrict__ gbias) {
    extern __shared__ __half sm[];
    const uint32_t sb = smem_u32(sm);
    const int tid = threadIdx.x, wid = tid >> 5, lane = tid & 31;
    const int g = lane >> 2, t4 = lane & 3;
    const int b = blockIdx.y, m0 = blockIdx.x * 64;
    const int lrow = lane & 15, lcol = (lane >> 4) * 8;

    const int w1m = (wid & 1) * 32, w1n = (wid >> 1) * 16;   // GEMM1 [32m x 16n]
    const int w2c = (wid >> 1) * 64, w2m = (wid & 1) * 32;   // GEMM2 [64c x 32m]

    #define SMB(idx) (sb + (uint32_t)(idx) * 2u)

    const int qrow = tid >> 3, qch = (tid & 7) * 8;
    const __half* gq = g_Q + ((size_t)b*NPIX + qrow)*CQ + qch;
    const uint32_t qd0 = qrow*LD + qch, qd1 = (qrow+32)*LD + qch;
    const int vrow = tid >> 3, vch = (tid & 7) * 8;
    const __half* gv = g_V + ((size_t)b*CC + vrow)*NPIX + vch;
    const uint32_t vd0 = vrow*LD + vch;

    {   // K prologue + stage 0 (one group)
        const __half* k = g_K + ((size_t)b*NPIX + m0)*CQ;
        #pragma unroll
        for (int r = 0; r < 2; r++) {
            int id = tid + 256*r, row = id >> 3, ch = (id & 7) * 8;
            cpa16(SMB(SM_K + row*LD + ch), k + (size_t)row*CQ + ch);
        }
        cpa16(SMB(Q_ST(0) + qd0), gq);
        cpa16(SMB(Q_ST(0) + qd1), gq + (size_t)32*CQ);
        #pragma unroll
        for (int r = 0; r < 8; r++)
            cpa16(SMB(V_ST(0) + vd0 + r*32*LD), gv + (size_t)r*32*NPIX);
        CP_COMMIT();
    }

    float acc[4][4][4];
    #pragma unroll
    for (int i = 0; i < 4; i++)
        #pragma unroll
        for (int j = 0; j < 4; j++)
            #pragma unroll
            for (int q = 0; q < 4; q++) acc[i][j][q] = 0.f;

    const __half* gq_n = gq + 64*CQ;
    const __half* gv_n = gv + 64;

    for (int it = 0; it < 64; ++it) {
        const int buf = it & 1;
        CP_WAIT0();
        __syncthreads();
        if (it < 63) {
            const uint32_t QN = Q_ST(buf ^ 1), VN = V_ST(buf ^ 1);
            cpa16(SMB(QN + qd0), gq_n);
            cpa16(SMB(QN + qd1), gq_n + (size_t)32*CQ);
            #pragma unroll
            for (int r = 0; r < 8; r++)
                cpa16(SMB(VN + vd0 + r*32*LD), gv_n + (size_t)r*32*NPIX);
            CP_COMMIT();
            gq_n += 64*CQ;
            gv_n += 64;
        }

        const uint32_t QO = Q_ST(buf), VO = V_ST(buf);

        // ---- GEMM1: S[m][n] = K·Q ----
        float sacc[2][2][4];
        #pragma unroll
        for (int i = 0; i < 2; i++)
            #pragma unroll
            for (int j = 0; j < 2; j++)
                #pragma unroll
                for (int q = 0; q < 4; q++) sacc[i][j][q] = 0.f;

        #pragma unroll
        for (int kk = 0; kk < 4; kk++) {
            const int C = kk * 16 + lcol;
            uint32_t k0[4], k1[4], qv[4];
            ldsm4(k0, SMB(SM_K + (w1m      + lrow)*LD + C));
            ldsm4(k1, SMB(SM_K + (w1m + 16 + lrow)*LD + C));
            ldsm4(qv, SMB(QO   + (w1n      + lrow)*LD + C));
            mmah(sacc[0][0], k0, qv[0], qv[2]);
            mmah(sacc[0][1], k0, qv[1], qv[3]);
            mmah(sacc[1][0], k1, qv[0], qv[2]);
            mmah(sacc[1][1], k1, qv[1], qv[3]);
        }

        // ---- elu + store S (fp16), layout [m][n] ----
        #pragma unroll
        for (int i = 0; i < 2; i++)
            #pragma unroll
            for (int j = 0; j < 2; j++) {
                int row = w1m + 16*i + g;
                int col = w1n + 8*j + t4*2;
                *(uint32_t*)&sm[SM_S + row*LD + col] =
                    packh(elu_raw(sacc[i][j][0]), elu_raw(sacc[i][j][1]));
                *(uint32_t*)&sm[SM_S + (row+8)*LD + col] =
                    packh(elu_raw(sacc[i][j][2]), elu_raw(sacc[i][j][3]));
            }
        __syncthreads();

        // ---- GEMM2: O[c][m] += V·S ----
        #pragma unroll
        for (int kk = 0; kk < 4; kk++) {
            const int C = kk * 16 + lcol;
            uint32_t vv[4][4], s0[4], s1[4];
            #pragma unroll
            for (int i = 0; i < 4; i++)
                ldsm4(vv[i], SMB(VO + (w2c + 16*i + lrow)*LD + C));
            ldsm4(s0, SMB(SM_S + (w2m      + lrow)*LD + C));
            ldsm4(s1, SMB(SM_S + (w2m + 16 + lrow)*LD + C));
            #pragma unroll
            for (int i = 0; i < 4; i++) {
                mmah(acc[i][0], vv[i], s0[0], s0[2]);
                mmah(acc[i][1], vv[i], s0[1], s0[3]);
                mmah(acc[i][2], vv[i], s1[0], s1[2]);
                mmah(acc[i][3], vv[i], s1[1], s1[3]);
            }
        }
    }

    // ---- epilogue: out = acc/4096 + gbias[c] ----
    const float inv = 1.0f / 4096.0f;
    #pragma unroll
    for (int i = 0; i < 4; i++) {
        int c  = w2c + 16*i + g;
        float b0 = gbias[c], b8 = gbias[c + 8];
        #pragma unroll
        for (int j = 0; j < 4; j++) {
            int m = m0 + w2m + 8*j + t4*2;
            float2 v0 = { fmaf(acc[i][j][0], inv, b0), fmaf(acc[i][j][1], inv, b0) };
            *(float2*)&out[((size_t)b*CC + c)*NPIX + m] = v0;
            float2 v1 = { fmaf(acc[i][j][2], inv, b8), fmaf(acc[i][j][3], inv, b8) };
            *(float2*)&out[((size_t)b*CC + c + 8)*NPIX + m] = v1;
        }
    }
}

// ================= launch =================
extern "C" void kernel_launch(void* const* d_in, const int* in_sizes, int n_in,
                              void* d_out, int out_size) {
    const float* x  = (const float*)d_in[0];
    const float* qw = (const float*)d_in[1];
    const float* qb = (const float*)d_in[2];
    const float* kw = (const float*)d_in[3];
    const float* kb = (const float*)d_in[4];
    const float* vw = (const float*)d_in[5];
    const float* vb = (const float*)d_in[6];
    const float* gw = (const float*)d_in[7];
    const float* gb = (const float*)d_in[8];
    float* out = (float*)d_out;

    cudaFuncSetAttribute(attn_mma, cudaFuncAttributeMaxDynamicSharedMemorySize, SMEM_BYTES);
    cudaFuncSetAttribute(proj_mma, cudaFuncAttributeMaxDynamicSharedMemorySize, PROJ_SMEM);

    prep_kernel<<<ROWS_ALL + 2048, 256>>>(x, qw, qb, kw, kb, vw, vb, gw);
    proj_mma<<<dim3(32, 3, BB), 256, PROJ_SMEM>>>(nullptr);
    attn_mma<<<dim3(64, BB), 256, SMEM_BYTES>>>(out, gb);
}